// round 1
// baseline (speedup 1.0000x reference)
#include <cuda_runtime.h>
#include <cub/cub.cuh>
#include <cstdint>

// Problem max sizes: E_e=500K, E_a=1M -> E=1.5M. Reserve a little headroom.
static constexpr int MAX_E = 1600000;

// Scratch (allocation-free: __device__ globals)
__device__ uint32_t g_keys_a[MAX_E];
__device__ uint32_t g_keys_b[MAX_E];
__device__ uint32_t g_vals_a[MAX_E];
__device__ uint32_t g_vals_b[MAX_E];
__device__ int      g_flags[MAX_E];
__device__ int      g_sums[MAX_E];
__device__ uint32_t g_segflag[MAX_E];      // per ORIGINAL edge: (seg<<1)|is_leader
__device__ unsigned char g_cub_temp[64 * 1024 * 1024];

// ---------------------------------------------------------------------------
// 1. init: uniq_r / uniq_c regions <- -1.0f
__global__ void k_init_out(float* __restrict__ out, int twoE) {
    int i = blockIdx.x * blockDim.x + threadIdx.x;
    if (i < twoE) out[i] = -1.0f;
}

// 2. build 32-bit sort keys: (row<<16)|col, payload = original edge id
__global__ void k_build_keys(const int* __restrict__ ei, const int* __restrict__ ai,
                             int Ee, int Ea) {
    int E = Ee + Ea;
    int i = blockIdx.x * blockDim.x + threadIdx.x;
    if (i >= E) return;
    int r, c;
    if (i < Ee) { r = ei[i];          c = ei[Ee + i]; }
    else        { int j = i - Ee; r = ai[j]; c = ai[Ea + j]; }
    g_keys_a[i] = ((uint32_t)r << 16) | (uint32_t)c;
    g_vals_a[i] = (uint32_t)i;
}

// 4. segment-boundary flags on sorted keys
__global__ void k_flags(int E) {
    int i = blockIdx.x * blockDim.x + threadIdx.x;
    if (i >= E) return;
    g_flags[i] = (i == 0) || (g_keys_b[i] != g_keys_b[i - 1]);
}

// 6. inverse map: original edge id -> (segment id, leader flag)
__global__ void k_invmap(int E) {
    int i = blockIdx.x * blockDim.x + threadIdx.x;
    if (i >= E) return;
    uint32_t orig = g_vals_b[i];
    g_segflag[orig] = ((uint32_t)(g_sums[i] - 1) << 1) | (uint32_t)g_flags[i];
}

// 7. leader scatter: half-warp per edge, original order (coalesced reads,
//    divergence-free), fused 32->64 projection for arrwp edges, float4 writes.
__global__ void k_scatter_leaders(const int* __restrict__ ei,
                                  const float* __restrict__ eattr,
                                  const int* __restrict__ ai,
                                  const float* __restrict__ aattr,
                                  const float* __restrict__ W,
                                  float* __restrict__ out, int Ee, int Ea) {
    __shared__ float Ws[64 * 33];  // padded: Ws[j*33+k], kills bank conflicts
    for (int idx = threadIdx.x; idx < 64 * 32; idx += blockDim.x)
        Ws[(idx >> 5) * 33 + (idx & 31)] = W[idx];
    __syncthreads();

    const int E = Ee + Ea;
    float* out_r    = out;
    float* out_c    = out + E;
    float* out_attr = out + 2 * (size_t)E;

    const int lane16 = threadIdx.x & 15;
    const unsigned hmask = 0xFFFFu << (threadIdx.x & 16);
    int hw  = (blockIdx.x * blockDim.x + threadIdx.x) >> 4;
    int nhw = (gridDim.x * blockDim.x) >> 4;

    for (int e = hw; e < E; e += nhw) {
        uint32_t sf = g_segflag[e];
        if (!(sf & 1u)) continue;           // not a segment leader (rare skip)
        int seg = (int)(sf >> 1);

        float4 v;
        if (e < Ee) {
            v = reinterpret_cast<const float4*>(eattr + (size_t)e * 64)[lane16];
        } else {
            const float* a = aattr + (size_t)(e - Ee) * 32;
            float a0 = a[2 * lane16];
            float a1 = a[2 * lane16 + 1];
            const float* w0 = &Ws[(4 * lane16) * 33];
            float4 acc = make_float4(0.f, 0.f, 0.f, 0.f);
            #pragma unroll
            for (int k = 0; k < 32; k++) {
                float ak = __shfl_sync(hmask, (k & 1) ? a1 : a0, k >> 1, 16);
                acc.x += ak * w0[k];
                acc.y += ak * w0[33 + k];
                acc.z += ak * w0[66 + k];
                acc.w += ak * w0[99 + k];
            }
            v = acc;
        }
        reinterpret_cast<float4*>(out_attr + (size_t)seg * 64)[lane16] = v;

        if (lane16 == 0) {
            int r, c;
            if (e < Ee) { r = ei[e];          c = ei[Ee + e]; }
            else        { int j = e - Ee; r = ai[j]; c = ai[Ea + j]; }
            out_r[seg] = (float)r;
            out_c[seg] = (float)c;
        }
    }
}

// 8. duplicate scatter: ~450 of 1.5M edges; runs AFTER leaders (stream order).
__global__ void k_scatter_dups(const float* __restrict__ eattr,
                               const float* __restrict__ aattr,
                               const float* __restrict__ W,
                               float* __restrict__ out, int Ee, int Ea) {
    int E = Ee + Ea;
    int e = blockIdx.x * blockDim.x + threadIdx.x;
    if (e >= E) return;
    uint32_t sf = g_segflag[e];
    if (sf & 1u) return;                    // leader -> nothing to do
    int seg = (int)(sf >> 1);
    float* orow = out + 2 * (size_t)E + (size_t)seg * 64;
    if (e < Ee) {
        const float* a = eattr + (size_t)e * 64;
        for (int j = 0; j < 64; j++) atomicAdd(orow + j, a[j]);
    } else {
        const float* a = aattr + (size_t)(e - Ee) * 32;
        float av[32];
        #pragma unroll
        for (int k = 0; k < 32; k++) av[k] = a[k];
        for (int j = 0; j < 64; j++) {
            float s = 0.f;
            #pragma unroll
            for (int k = 0; k < 32; k++) s += av[k] * W[j * 32 + k];
            atomicAdd(orow + j, s);
        }
    }
}

// 9. zero attr rows [num_unique, E) and write num_unique as the final element
__global__ void k_tail(float* __restrict__ out, int E) {
    int nu = g_sums[E - 1];
    float* out_attr = out + 2 * (size_t)E;
    size_t start = (size_t)nu * 64;
    size_t end   = (size_t)E * 64;
    for (size_t i = start + blockIdx.x * blockDim.x + threadIdx.x; i < end;
         i += (size_t)gridDim.x * blockDim.x)
        out_attr[i] = 0.0f;
    if (blockIdx.x == 0 && threadIdx.x == 0)
        out[2 * (size_t)E + (size_t)E * 64] = (float)nu;
}

// ---------------------------------------------------------------------------
extern "C" void kernel_launch(void* const* d_in, const int* in_sizes, int n_in,
                              void* d_out, int out_size) {
    (void)n_in; (void)out_size;
    const int*   ei    = (const int*)d_in[0];     // edge_index  (2, E_e)
    const float* eattr = (const float*)d_in[1];   // edge_attr   (E_e, 64)
    const int*   ai    = (const int*)d_in[2];     // arrwp_index (2, E_a)
    const float* aattr = (const float*)d_in[3];   // arrwp_attr  (E_a, 32)
    const float* W     = (const float*)d_in[4];   // W           (64, 32)
    const int Ee = in_sizes[0] / 2;
    const int Ea = in_sizes[2] / 2;
    const int E  = Ee + Ea;
    float* out = (float*)d_out;

    void *pka, *pkb, *pva, *pvb, *pf, *ps, *ptmp;
    cudaGetSymbolAddress(&pka, g_keys_a);
    cudaGetSymbolAddress(&pkb, g_keys_b);
    cudaGetSymbolAddress(&pva, g_vals_a);
    cudaGetSymbolAddress(&pvb, g_vals_b);
    cudaGetSymbolAddress(&pf,  g_flags);
    cudaGetSymbolAddress(&ps,  g_sums);
    cudaGetSymbolAddress(&ptmp, g_cub_temp);

    const int T = 256;
    k_init_out<<<(2 * E + T - 1) / T, T>>>(out, 2 * E);
    k_build_keys<<<(E + T - 1) / T, T>>>(ei, ai, Ee, Ea);

    size_t tb = sizeof(g_cub_temp);
    cub::DeviceRadixSort::SortPairs(ptmp, tb,
                                    (const uint32_t*)pka, (uint32_t*)pkb,
                                    (const uint32_t*)pva, (uint32_t*)pvb,
                                    E, 0, 32);

    k_flags<<<(E + T - 1) / T, T>>>(E);

    size_t tb2 = sizeof(g_cub_temp);
    cub::DeviceScan::InclusiveSum(ptmp, tb2, (const int*)pf, (int*)ps, E);

    k_invmap<<<(E + T - 1) / T, T>>>(E);
    k_scatter_leaders<<<2048, T>>>(ei, eattr, ai, aattr, W, out, Ee, Ea);
    k_scatter_dups<<<(E + T - 1) / T, T>>>(eattr, aattr, W, out, Ee, Ea);
    k_tail<<<256, T>>>(out, E);
}